// round 2
// baseline (speedup 1.0000x reference)
#include <cuda_runtime.h>
#include <cuda_bf16.h>
#include <math.h>
#include <stdint.h>

// ---------------------------------------------------------------------------
// PredictorLG fused MLP:  LN -> (GEMM+GELU)x3 -> GEMM(->2) -> log_softmax
// x: [M=2, B=64, N=2048, C=384]  -> out [2,64,2048,2] fp32
// Strategy: 128 rows per CTA, activations in SMEM (bf16), weights pre-packed
// into mma.sync m16n8k16 B-fragment layout in a __device__ scratch buffer.
// ---------------------------------------------------------------------------

#define ROWS_TILE   128
#define NTHREADS    256
#define LD          392           // padded activation row stride (halfs)
#define RTOT        262144        // M*B*N rows
#define ROWS_PER_M  131072

// weight sizes per modality (elements)
#define S1 (384*384)
#define S2 (384*192)
#define S3 (192*96)
#define MOD_STRIDE (S1+S2+S3)     // 239616 halfs per modality
#define OFF_L2 (S1)
#define OFF_L3 (S1+S2)

__device__ __nv_bfloat16 g_packedW[2 * MOD_STRIDE];

// ---------------------------------------------------------------------------
// Weight repack: W[k][n] fp32 (row-major [K,N]) -> bf16 B-fragment layout:
//   dst = base + ((nt*(K/16)+kt)*32 + lane)*4 + reg*2 + i
//   lane = (n%8)*4 + ((k%8)>>1);  reg = (k>>3)&1;  i = k&1
// so each thread's B-frag for one (kt,nt) is 4 contiguous halfs (one uint2).
// ---------------------------------------------------------------------------
__global__ void pack_weights_kernel(const float* __restrict__ W1,
                                    const float* __restrict__ W2,
                                    const float* __restrict__ W3) {
    int idx = blockIdx.x * blockDim.x + threadIdx.x;
    const float* src;
    int K, N, r, m, layerOff;
    if (idx < 2 * S1) {
        m = idx / S1; r = idx % S1; K = 384; N = 384;
        src = W1 + m * S1; layerOff = 0;
    } else if (idx < 2 * S1 + 2 * S2) {
        int e = idx - 2 * S1;
        m = e / S2; r = e % S2; K = 384; N = 192;
        src = W2 + m * S2; layerOff = OFF_L2;
    } else if (idx < 2 * (S1 + S2 + S3)) {
        int e = idx - 2 * S1 - 2 * S2;
        m = e / S3; r = e % S3; K = 192; N = 96;
        src = W3 + m * S3; layerOff = OFF_L3;
    } else {
        return;
    }
    int k = r / N, n = r % N;
    int kt = k >> 4, nt = n >> 3;
    int lane = (n & 7) * 4 + ((k & 7) >> 1);
    int reg  = (k >> 3) & 1;
    int i    = k & 1;
    int dst  = m * MOD_STRIDE + layerOff +
               ((nt * (K / 16) + kt) * 32 + lane) * 4 + reg * 2 + i;
    g_packedW[dst] = __float2bfloat16(src[k * N + n]);
}

// ---------------------------------------------------------------------------
// mma / ldmatrix helpers
// ---------------------------------------------------------------------------
__device__ __forceinline__ void mma16816(float c[4], const unsigned a[4],
                                         const unsigned b[2]) {
    asm volatile(
        "mma.sync.aligned.m16n8k16.row.col.f32.bf16.bf16.f32 "
        "{%0,%1,%2,%3}, {%4,%5,%6,%7}, {%8,%9}, {%0,%1,%2,%3};\n"
        : "+f"(c[0]), "+f"(c[1]), "+f"(c[2]), "+f"(c[3])
        : "r"(a[0]), "r"(a[1]), "r"(a[2]), "r"(a[3]), "r"(b[0]), "r"(b[1]));
}

__device__ __forceinline__ void ldmatrix_x4(unsigned r[4], uint32_t addr) {
    asm volatile(
        "ldmatrix.sync.aligned.m8n8.x4.shared.b16 {%0,%1,%2,%3}, [%4];\n"
        : "=r"(r[0]), "=r"(r[1]), "=r"(r[2]), "=r"(r[3])
        : "r"(addr));
}

__device__ __forceinline__ float gelu_erf(float v) {
    return 0.5f * v * (1.0f + erff(v * 0.70710678118654752f));
}

// ---------------------------------------------------------------------------
// One GEMM layer: out = gelu(in[128,K] @ W[K,N] + bias), bf16 in/out, fp32 acc.
// Warp grid: 4 (m) x 2 (n). Each pass covers CHUNK columns; warp gets CHUNK/2.
// ---------------------------------------------------------------------------
template <int K, int N, int CHUNK>
__device__ __forceinline__ void gemm_layer(const __nv_bfloat16* inBuf,
                                           __nv_bfloat16* outBuf,
                                           const __nv_bfloat16* __restrict__ Wp,
                                           const float* __restrict__ s_bias) {
    constexpr int NPASS = N / CHUNK;
    constexpr int NF = CHUNK / 16;   // n-frags per warp per pass
    constexpr int KT = K / 16;

    const int tid  = threadIdx.x;
    const int lane = tid & 31;
    const int wid  = tid >> 5;
    const int wm   = wid & 3;        // row group: 32 rows
    const int wn   = wid >> 2;       // col group

    uint32_t sA = (uint32_t)__cvta_generic_to_shared(inBuf);
    const int arow     = wm * 32 + (lane & 15);
    const int acol_off = (lane >> 4) * 8;

#pragma unroll
    for (int p = 0; p < NPASS; ++p) {
        float acc[2][NF][4];
#pragma unroll
        for (int mi = 0; mi < 2; ++mi)
#pragma unroll
            for (int nf = 0; nf < NF; ++nf)
#pragma unroll
                for (int q = 0; q < 4; ++q) acc[mi][nf][q] = 0.f;

        const int colbase = p * CHUNK + wn * (CHUNK / 2);
        const int ntbase  = colbase >> 3;

#pragma unroll
        for (int kt = 0; kt < KT; ++kt) {
            unsigned a[2][4];
            uint32_t addr0 = sA + (uint32_t)((arow * LD + kt * 16 + acol_off) * 2);
            ldmatrix_x4(a[0], addr0);
            ldmatrix_x4(a[1], addr0 + 16 * LD * 2);

            unsigned bfr[NF][2];
#pragma unroll
            for (int nf = 0; nf < NF; ++nf) {
                const uint2* bp = (const uint2*)(Wp +
                    (((size_t)(ntbase + nf) * KT + kt) * 32 + lane) * 4);
                uint2 v = __ldg(bp);
                bfr[nf][0] = v.x;
                bfr[nf][1] = v.y;
            }
#pragma unroll
            for (int nf = 0; nf < NF; ++nf) {
                mma16816(acc[0][nf], a[0], bfr[nf]);
                mma16816(acc[1][nf], a[1], bfr[nf]);
            }
        }

        // epilogue: bias + gelu + bf16 store
        const int r0 = wm * 32 + (lane >> 2);
        const int cb = colbase + (lane & 3) * 2;
#pragma unroll
        for (int nf = 0; nf < NF; ++nf) {
            const int c = cb + nf * 8;
            const float b0 = s_bias[c];
            const float b1 = s_bias[c + 1];
#pragma unroll
            for (int mi = 0; mi < 2; ++mi) {
                const int row = r0 + mi * 16;
                float v0 = gelu_erf(acc[mi][nf][0] + b0);
                float v1 = gelu_erf(acc[mi][nf][1] + b1);
                float v2 = gelu_erf(acc[mi][nf][2] + b0);
                float v3 = gelu_erf(acc[mi][nf][3] + b1);
                *(__nv_bfloat162*)(outBuf + row * LD + c) =
                    __floats2bfloat162_rn(v0, v1);
                *(__nv_bfloat162*)(outBuf + (row + 8) * LD + c) =
                    __floats2bfloat162_rn(v2, v3);
            }
        }
    }
}

// ---------------------------------------------------------------------------
// Fused kernel
// ---------------------------------------------------------------------------
__global__ void __launch_bounds__(NTHREADS, 1)
fused_mlp_kernel(const float* __restrict__ x,
                 const float* __restrict__ ln_g,
                 const float* __restrict__ ln_b,
                 const float* __restrict__ b1,
                 const float* __restrict__ b2,
                 const float* __restrict__ b3,
                 const float* __restrict__ W4,
                 const float* __restrict__ b4,
                 float* __restrict__ out) {
    extern __shared__ __align__(16) char smem_raw[];
    __nv_bfloat16* bufA = (__nv_bfloat16*)smem_raw;                 // [128][392]
    __nv_bfloat16* bufB = bufA + ROWS_TILE * LD;                    // [128][392]
    float* s_bias = (float*)(bufB + ROWS_TILE * LD);                // [384]

    const int tid  = threadIdx.x;
    const int lane = tid & 31;
    const int wid  = tid >> 5;
    const int tile = blockIdx.x;
    const long row0 = (long)tile * ROWS_TILE;
    const int m = (int)(row0 / ROWS_PER_M);   // tile never straddles modalities

    // ------------------- Stage 0: LayerNorm -> bufA (bf16) -----------------
    {
        // per-lane LN params: 3 float4 = 12 channels, cols = (j*32+lane)*4 + t
        float4 g4[3], bb4[3];
#pragma unroll
        for (int j = 0; j < 3; ++j) {
            g4[j]  = ((const float4*)(ln_g + m * 384))[j * 32 + lane];
            bb4[j] = ((const float4*)(ln_b + m * 384))[j * 32 + lane];
        }
        for (int r = wid; r < ROWS_TILE; r += 8) {
            const float4* xr = (const float4*)(x + (row0 + r) * 384);
            float4 v[3];
            float s = 0.f, q = 0.f;
#pragma unroll
            for (int j = 0; j < 3; ++j) {
                v[j] = xr[j * 32 + lane];
                s += v[j].x + v[j].y + v[j].z + v[j].w;
                q += v[j].x * v[j].x + v[j].y * v[j].y +
                     v[j].z * v[j].z + v[j].w * v[j].w;
            }
#pragma unroll
            for (int off = 16; off; off >>= 1) {
                s += __shfl_xor_sync(0xffffffffu, s, off);
                q += __shfl_xor_sync(0xffffffffu, q, off);
            }
            const float mu   = s * (1.0f / 384.0f);
            const float var  = q * (1.0f / 384.0f) - mu * mu;
            const float rinv = rsqrtf(var + 1e-5f);
#pragma unroll
            for (int j = 0; j < 3; ++j) {
                const int c = (j * 32 + lane) * 4;
                float y0 = (v[j].x - mu) * rinv * g4[j].x + bb4[j].x;
                float y1 = (v[j].y - mu) * rinv * g4[j].y + bb4[j].y;
                float y2 = (v[j].z - mu) * rinv * g4[j].z + bb4[j].z;
                float y3 = (v[j].w - mu) * rinv * g4[j].w + bb4[j].w;
                *(__nv_bfloat162*)(bufA + r * LD + c)     = __floats2bfloat162_rn(y0, y1);
                *(__nv_bfloat162*)(bufA + r * LD + c + 2) = __floats2bfloat162_rn(y2, y3);
            }
        }
    }

    const __nv_bfloat16* WpBase = g_packedW + (size_t)m * MOD_STRIDE;

    // ------------------- Layer 1: 384 -> 384 -------------------------------
    __syncthreads();
    if (tid < 384) s_bias[tid] = b1[m * 384 + tid];
    __syncthreads();
    gemm_layer<384, 384, 192>(bufA, bufB, WpBase, s_bias);

    // ------------------- Layer 2: 384 -> 192 -------------------------------
    __syncthreads();
    if (tid < 192) s_bias[tid] = b2[m * 192 + tid];
    __syncthreads();
    gemm_layer<384, 192, 192>(bufB, bufA, WpBase + OFF_L2, s_bias);

    // ------------------- Layer 3: 192 -> 96 --------------------------------
    __syncthreads();
    if (tid < 96) s_bias[tid] = b3[m * 96 + tid];
    __syncthreads();
    gemm_layer<192, 96, 96>(bufA, bufB, WpBase + OFF_L3, s_bias);

    // ------------------- Layer 4: 96 -> 2 + log_softmax --------------------
    __syncthreads();
    if (tid < ROWS_TILE) {
        const int r = tid;
        const float* w4 = W4 + m * 96 * 2;
        float z0 = b4[m * 2 + 0];
        float z1 = b4[m * 2 + 1];
        const __nv_bfloat16* hrow = bufB + r * LD;
#pragma unroll 8
        for (int k = 0; k < 96; ++k) {
            float a = __bfloat162float(hrow[k]);
            z0 += a * w4[k * 2 + 0];
            z1 += a * w4[k * 2 + 1];
        }
        const float mx  = fmaxf(z0, z1);
        const float lse = mx + logf(expf(z0 - mx) + expf(z1 - mx));
        float* o = out + (row0 + r) * 2;
        o[0] = z0 - lse;
        o[1] = z1 - lse;
    }
}

// ---------------------------------------------------------------------------
// Launch
// ---------------------------------------------------------------------------
extern "C" void kernel_launch(void* const* d_in, const int* in_sizes, int n_in,
                              void* d_out, int out_size) {
    const float* x    = (const float*)d_in[0];
    const float* ln_g = (const float*)d_in[1];
    const float* ln_b = (const float*)d_in[2];
    const float* W1   = (const float*)d_in[3];
    const float* b1   = (const float*)d_in[4];
    const float* W2   = (const float*)d_in[5];
    const float* b2   = (const float*)d_in[6];
    const float* W3   = (const float*)d_in[7];
    const float* b3   = (const float*)d_in[8];
    const float* W4   = (const float*)d_in[9];
    const float* b4   = (const float*)d_in[10];
    float* out        = (float*)d_out;

    // 1) repack weights to bf16 fragment layout (cheap, ~480k threads)
    const int packTotal = 2 * MOD_STRIDE;
    pack_weights_kernel<<<(packTotal + 255) / 256, 256>>>(W1, W2, W3);

    // 2) fused MLP
    const int smem_bytes = 2 * ROWS_TILE * LD * (int)sizeof(__nv_bfloat16)
                         + 384 * (int)sizeof(float);
    cudaFuncSetAttribute(fused_mlp_kernel,
                         cudaFuncAttributeMaxDynamicSharedMemorySize, smem_bytes);
    fused_mlp_kernel<<<RTOT / ROWS_TILE, NTHREADS, smem_bytes>>>(
        x, ln_g, ln_b, b1, b2, b3, W4, b4, out);
}

// round 3
// speedup vs baseline: 1.7361x; 1.7361x over previous
#include <cuda_runtime.h>
#include <cuda_bf16.h>
#include <math.h>
#include <stdint.h>

// ---------------------------------------------------------------------------
// PredictorLG fused MLP:  LN -> (GEMM+GELU)x3 -> GEMM(->2) -> log_softmax
// x: [M=2, B=64, N=2048, C=384]  -> out [2,64,2048,2] fp32
// R3: 64 rows/CTA, 2 CTAs/SM (occ 2x), warp grid 2x4, pipelined B loads.
// ---------------------------------------------------------------------------

#define ROWS_TILE   64
#define NTHREADS    256
#define LD          392           // padded activation row stride (halfs)
#define RTOT        262144        // M*B*N rows
#define ROWS_PER_M  131072

// weight sizes per modality (elements)
#define S1 (384*384)
#define S2 (384*192)
#define S3 (192*96)
#define MOD_STRIDE (S1+S2+S3)     // halfs per modality
#define OFF_L2 (S1)
#define OFF_L3 (S1+S2)

__device__ __nv_bfloat16 g_packedW[2 * MOD_STRIDE];

// ---------------------------------------------------------------------------
// Weight repack: W[k][n] fp32 (row-major [K,N]) -> bf16 B-fragment layout:
//   dst = base + ((nt*(K/16)+kt)*32 + lane)*4 + reg*2 + i
//   lane = (n%8)*4 + ((k%8)>>1);  reg = (k>>3)&1;  i = k&1
// ---------------------------------------------------------------------------
__global__ void pack_weights_kernel(const float* __restrict__ W1,
                                    const float* __restrict__ W2,
                                    const float* __restrict__ W3) {
    int idx = blockIdx.x * blockDim.x + threadIdx.x;
    const float* src;
    int K, N, r, m, layerOff;
    if (idx < 2 * S1) {
        m = idx / S1; r = idx % S1; K = 384; N = 384;
        src = W1 + m * S1; layerOff = 0;
    } else if (idx < 2 * S1 + 2 * S2) {
        int e = idx - 2 * S1;
        m = e / S2; r = e % S2; K = 384; N = 192;
        src = W2 + m * S2; layerOff = OFF_L2;
    } else if (idx < 2 * (S1 + S2 + S3)) {
        int e = idx - 2 * S1 - 2 * S2;
        m = e / S3; r = e % S3; K = 192; N = 96;
        src = W3 + m * S3; layerOff = OFF_L3;
    } else {
        return;
    }
    int k = r / N, n = r % N;
    int kt = k >> 4, nt = n >> 3;
    int lane = (n & 7) * 4 + ((k & 7) >> 1);
    int reg  = (k >> 3) & 1;
    int i    = k & 1;
    int dst  = m * MOD_STRIDE + layerOff +
               ((nt * (K / 16) + kt) * 32 + lane) * 4 + reg * 2 + i;
    g_packedW[dst] = __float2bfloat16(src[k * N + n]);
}

// ---------------------------------------------------------------------------
// mma / ldmatrix helpers
// ---------------------------------------------------------------------------
__device__ __forceinline__ void mma16816(float c[4], const unsigned a[4],
                                         const unsigned b0, const unsigned b1) {
    asm volatile(
        "mma.sync.aligned.m16n8k16.row.col.f32.bf16.bf16.f32 "
        "{%0,%1,%2,%3}, {%4,%5,%6,%7}, {%8,%9}, {%0,%1,%2,%3};\n"
        : "+f"(c[0]), "+f"(c[1]), "+f"(c[2]), "+f"(c[3])
        : "r"(a[0]), "r"(a[1]), "r"(a[2]), "r"(a[3]), "r"(b0), "r"(b1));
}

__device__ __forceinline__ void ldmatrix_x4(unsigned r[4], uint32_t addr) {
    asm volatile(
        "ldmatrix.sync.aligned.m8n8.x4.shared.b16 {%0,%1,%2,%3}, [%4];\n"
        : "=r"(r[0]), "=r"(r[1]), "=r"(r[2]), "=r"(r[3])
        : "r"(addr));
}

__device__ __forceinline__ float gelu_erf(float v) {
    return 0.5f * v * (1.0f + erff(v * 0.70710678118654752f));
}

// ---------------------------------------------------------------------------
// One GEMM layer: out = gelu(in[64,K] @ W[K,N] + bias), bf16 in/out, fp32 acc.
// Warp grid: 2 (m, 32 rows each) x 4 (n). Per pass each warp owns CHUNK/4 cols.
// B-fragment global loads are software-pipelined one kt ahead.
// ---------------------------------------------------------------------------
template <int K, int N, int CHUNK>
__device__ __forceinline__ void gemm_layer(const __nv_bfloat16* inBuf,
                                           __nv_bfloat16* outBuf,
                                           const __nv_bfloat16* __restrict__ Wp,
                                           const float* __restrict__ s_bias) {
    constexpr int NPASS = N / CHUNK;
    constexpr int CW = CHUNK / 4;    // cols per warp per pass
    constexpr int NF = CW / 8;       // 8-col b-frags per warp per pass
    constexpr int KT = K / 16;

    const int tid  = threadIdx.x;
    const int lane = tid & 31;
    const int wid  = tid >> 5;
    const int wm   = wid & 1;        // row group: 32 rows
    const int wn   = wid >> 1;       // col group (0..3)

    uint32_t sA = (uint32_t)__cvta_generic_to_shared(inBuf);
    const int arow     = wm * 32 + (lane & 15);
    const int acol_off = (lane >> 4) * 8;
    const uint32_t aBase = sA + (uint32_t)((arow * LD + acol_off) * 2);

#pragma unroll
    for (int p = 0; p < NPASS; ++p) {
        float acc[2][NF][4];
#pragma unroll
        for (int mi = 0; mi < 2; ++mi)
#pragma unroll
            for (int nf = 0; nf < NF; ++nf)
#pragma unroll
                for (int q = 0; q < 4; ++q) acc[mi][nf][q] = 0.f;

        const int colbase = p * CHUNK + wn * CW;
        const int ntbase  = colbase >> 3;
        // per-frag base pointers (kt stride = 32*4 halfs = 256B)
        const uint2* bbase = (const uint2*)(Wp + ((size_t)ntbase * KT * 32 + lane) * 4);

        uint2 bcur[NF];
#pragma unroll
        for (int nf = 0; nf < NF; ++nf)
            bcur[nf] = __ldg(bbase + (size_t)nf * KT * 32);

#pragma unroll
        for (int kt = 0; kt < KT; ++kt) {
            unsigned a[2][4];
            uint32_t addr0 = aBase + (uint32_t)(kt * 32);
            ldmatrix_x4(a[0], addr0);
            ldmatrix_x4(a[1], addr0 + 16 * LD * 2);

            uint2 bnxt[NF];
            if (kt + 1 < KT) {
#pragma unroll
                for (int nf = 0; nf < NF; ++nf)
                    bnxt[nf] = __ldg(bbase + (size_t)nf * KT * 32 + (kt + 1) * 32);
            }
#pragma unroll
            for (int nf = 0; nf < NF; ++nf) {
                mma16816(acc[0][nf], a[0], bcur[nf].x, bcur[nf].y);
                mma16816(acc[1][nf], a[1], bcur[nf].x, bcur[nf].y);
            }
            if (kt + 1 < KT) {
#pragma unroll
                for (int nf = 0; nf < NF; ++nf) bcur[nf] = bnxt[nf];
            }
        }

        // epilogue: bias + gelu + bf16 store
        const int r0 = wm * 32 + (lane >> 2);
        const int cb = colbase + (lane & 3) * 2;
#pragma unroll
        for (int nf = 0; nf < NF; ++nf) {
            const int c = cb + nf * 8;
            const float b0 = s_bias[c];
            const float b1 = s_bias[c + 1];
#pragma unroll
            for (int mi = 0; mi < 2; ++mi) {
                const int row = r0 + mi * 16;
                float v0 = gelu_erf(acc[mi][nf][0] + b0);
                float v1 = gelu_erf(acc[mi][nf][1] + b1);
                float v2 = gelu_erf(acc[mi][nf][2] + b0);
                float v3 = gelu_erf(acc[mi][nf][3] + b1);
                *(__nv_bfloat162*)(outBuf + row * LD + c) =
                    __floats2bfloat162_rn(v0, v1);
                *(__nv_bfloat162*)(outBuf + (row + 8) * LD + c) =
                    __floats2bfloat162_rn(v2, v3);
            }
        }
    }
}

// ---------------------------------------------------------------------------
// Fused kernel
// ---------------------------------------------------------------------------
__global__ void __launch_bounds__(NTHREADS, 2)
fused_mlp_kernel(const float* __restrict__ x,
                 const float* __restrict__ ln_g,
                 const float* __restrict__ ln_b,
                 const float* __restrict__ b1,
                 const float* __restrict__ b2,
                 const float* __restrict__ b3,
                 const float* __restrict__ W4,
                 const float* __restrict__ b4,
                 float* __restrict__ out) {
    extern __shared__ __align__(16) char smem_raw[];
    __nv_bfloat16* bufA = (__nv_bfloat16*)smem_raw;                 // [64][392]
    __nv_bfloat16* bufB = bufA + ROWS_TILE * LD;                    // [64][392]
    float* s_bias = (float*)(bufB + ROWS_TILE * LD);                // [384]

    const int tid  = threadIdx.x;
    const int lane = tid & 31;
    const int wid  = tid >> 5;
    const long row0 = (long)blockIdx.x * ROWS_TILE;
    const int m = (int)(row0 / ROWS_PER_M);   // tile never straddles modalities

    // ------------------- Stage 0: LayerNorm -> bufA (bf16) -----------------
    {
        float4 g4[3], bb4[3];
#pragma unroll
        for (int j = 0; j < 3; ++j) {
            g4[j]  = ((const float4*)(ln_g + m * 384))[j * 32 + lane];
            bb4[j] = ((const float4*)(ln_b + m * 384))[j * 32 + lane];
        }
#pragma unroll
        for (int r = wid; r < ROWS_TILE; r += 8) {
            const float4* xr = (const float4*)(x + (row0 + r) * 384);
            float4 v[3];
            float s = 0.f, q = 0.f;
#pragma unroll
            for (int j = 0; j < 3; ++j) {
                v[j] = xr[j * 32 + lane];
                s += v[j].x + v[j].y + v[j].z + v[j].w;
                q += v[j].x * v[j].x + v[j].y * v[j].y +
                     v[j].z * v[j].z + v[j].w * v[j].w;
            }
#pragma unroll
            for (int off = 16; off; off >>= 1) {
                s += __shfl_xor_sync(0xffffffffu, s, off);
                q += __shfl_xor_sync(0xffffffffu, q, off);
            }
            const float mu   = s * (1.0f / 384.0f);
            const float var  = q * (1.0f / 384.0f) - mu * mu;
            const float rinv = rsqrtf(var + 1e-5f);
#pragma unroll
            for (int j = 0; j < 3; ++j) {
                const int c = (j * 32 + lane) * 4;
                float y0 = (v[j].x - mu) * rinv * g4[j].x + bb4[j].x;
                float y1 = (v[j].y - mu) * rinv * g4[j].y + bb4[j].y;
                float y2 = (v[j].z - mu) * rinv * g4[j].z + bb4[j].z;
                float y3 = (v[j].w - mu) * rinv * g4[j].w + bb4[j].w;
                *(__nv_bfloat162*)(bufA + r * LD + c)     = __floats2bfloat162_rn(y0, y1);
                *(__nv_bfloat162*)(bufA + r * LD + c + 2) = __floats2bfloat162_rn(y2, y3);
            }
        }
    }

    const __nv_bfloat16* WpBase = g_packedW + (size_t)m * MOD_STRIDE;

    // ------------------- Layer 1: 384 -> 384 -------------------------------
    __syncthreads();
    for (int i = tid; i < 384; i += NTHREADS) s_bias[i] = b1[m * 384 + i];
    __syncthreads();
    gemm_layer<384, 384, 192>(bufA, bufB, WpBase, s_bias);

    // ------------------- Layer 2: 384 -> 192 -------------------------------
    __syncthreads();
    if (tid < 192) s_bias[tid] = b2[m * 192 + tid];
    __syncthreads();
    gemm_layer<384, 192, 192>(bufB, bufA, WpBase + OFF_L2, s_bias);

    // ------------------- Layer 3: 192 -> 96 --------------------------------
    __syncthreads();
    if (tid < 96) s_bias[tid] = b3[m * 96 + tid];
    __syncthreads();
    gemm_layer<192, 96, 96>(bufA, bufB, WpBase + OFF_L3, s_bias);

    // ------------------- Layer 4: 96 -> 2 + log_softmax --------------------
    __syncthreads();
    {
        const int r    = tid >> 2;       // 64 rows, 4 threads per row
        const int part = tid & 3;
        const float* w4 = W4 + m * 96 * 2;
        const __nv_bfloat16* hrow = bufB + r * LD;
        float z0 = 0.f, z1 = 0.f;
#pragma unroll
        for (int kk = 0; kk < 24; ++kk) {
            const int k = part * 24 + kk;
            float a = __bfloat162float(hrow[k]);
            z0 += a * w4[k * 2 + 0];
            z1 += a * w4[k * 2 + 1];
        }
        z0 += __shfl_xor_sync(0xffffffffu, z0, 1);
        z0 += __shfl_xor_sync(0xffffffffu, z0, 2);
        z1 += __shfl_xor_sync(0xffffffffu, z1, 1);
        z1 += __shfl_xor_sync(0xffffffffu, z1, 2);
        if (part == 0) {
            z0 += b4[m * 2 + 0];
            z1 += b4[m * 2 + 1];
            const float mx  = fmaxf(z0, z1);
            const float lse = mx + logf(expf(z0 - mx) + expf(z1 - mx));
            float* o = out + (row0 + r) * 2;
            o[0] = z0 - lse;
            o[1] = z1 - lse;
        }
    }
}

// ---------------------------------------------------------------------------
// Launch
// ---------------------------------------------------------------------------
extern "C" void kernel_launch(void* const* d_in, const int* in_sizes, int n_in,
                              void* d_out, int out_size) {
    const float* x    = (const float*)d_in[0];
    const float* ln_g = (const float*)d_in[1];
    const float* ln_b = (const float*)d_in[2];
    const float* W1   = (const float*)d_in[3];
    const float* b1   = (const float*)d_in[4];
    const float* W2   = (const float*)d_in[5];
    const float* b2   = (const float*)d_in[6];
    const float* W3   = (const float*)d_in[7];
    const float* b3   = (const float*)d_in[8];
    const float* W4   = (const float*)d_in[9];
    const float* b4   = (const float*)d_in[10];
    float* out        = (float*)d_out;

    const int packTotal = 2 * MOD_STRIDE;
    pack_weights_kernel<<<(packTotal + 255) / 256, 256>>>(W1, W2, W3);

    const int smem_bytes = 2 * ROWS_TILE * LD * (int)sizeof(__nv_bfloat16)
                         + 384 * (int)sizeof(float);
    cudaFuncSetAttribute(fused_mlp_kernel,
                         cudaFuncAttributeMaxDynamicSharedMemorySize, smem_bytes);
    fused_mlp_kernel<<<RTOT / ROWS_TILE, NTHREADS, smem_bytes>>>(
        x, ln_g, ln_b, b1, b2, b3, W4, b4, out);
}

// round 5
// speedup vs baseline: 1.7685x; 1.0187x over previous
#include <cuda_runtime.h>
#include <cuda_bf16.h>
#include <math.h>
#include <stdint.h>

// ---------------------------------------------------------------------------
// PredictorLG fused MLP:  LN -> (GEMM+GELU)x3 -> GEMM(->2) -> log_softmax
// x: [M=2, B=64, N=2048, C=384]  -> out [2,64,2048,2] fp32
// R5: HMMA path (tcgen05 rejected by harness PTX target). 64 rows/CTA,
// 2 CTAs/SM. Pair-kt packed B + LDG.128 + depth-2-pair (4 kt) prefetch to
// cover L2 latency (~240cyc). Warp grid 2(m) x 4(n), NF=4/3.
// ---------------------------------------------------------------------------

#define ROWS_TILE   64
#define NTHREADS    256
#define LD          392           // padded activation row stride (halfs)
#define RTOT        262144
#define ROWS_PER_M  131072

#define S1 (384*384)
#define S2 (384*192)
#define S3 (192*96)
#define MOD_STRIDE (S1+S2+S3)
#define OFF_L2 (S1)
#define OFF_L3 (S1+S2)

__device__ __align__(16) __nv_bfloat16 g_packedW[2 * MOD_STRIDE];

// ---------------------------------------------------------------------------
// Weight repack: W[k][n] fp32 -> pair-kt B-fragment layout:
//   ktp = kt>>1 (kt = k>>4), per-lane 16B = fragments for kt pair.
//   dst = base + ((nt*KTP + ktp)*32 + lane)*8 + (kt&1)*4 + reg*2 + i
//   lane = (n%8)*4 + ((k%8)>>1);  reg = (k>>3)&1;  i = k&1
// ---------------------------------------------------------------------------
__global__ void pack_weights_kernel(const float* __restrict__ W1,
                                    const float* __restrict__ W2,
                                    const float* __restrict__ W3) {
    int idx = blockIdx.x * blockDim.x + threadIdx.x;
    const float* src;
    int K, N, r, m, layerOff;
    if (idx < 2 * S1) {
        m = idx / S1; r = idx % S1; K = 384; N = 384;
        src = W1 + m * S1; layerOff = 0;
    } else if (idx < 2 * (S1 + S2)) {
        int e = idx - 2 * S1;
        m = e / S2; r = e % S2; K = 384; N = 192;
        src = W2 + m * S2; layerOff = OFF_L2;
    } else if (idx < 2 * (S1 + S2 + S3)) {
        int e = idx - 2 * (S1 + S2);
        m = e / S3; r = e % S3; K = 192; N = 96;
        src = W3 + m * S3; layerOff = OFF_L3;
    } else {
        return;
    }
    int k = r / N, n = r % N;
    int kt  = k >> 4;
    int ktp = kt >> 1;
    int KTP = K >> 5;                 // K/32
    int nt  = n >> 3;
    int lane = (n & 7) * 4 + ((k & 7) >> 1);
    int reg  = (k >> 3) & 1;
    int i    = k & 1;
    int dst  = m * MOD_STRIDE + layerOff +
               ((nt * KTP + ktp) * 32 + lane) * 8 + (kt & 1) * 4 + reg * 2 + i;
    g_packedW[dst] = __float2bfloat16(src[k * N + n]);
}

// ---------------------------------------------------------------------------
// mma / ldmatrix helpers
// ---------------------------------------------------------------------------
__device__ __forceinline__ void mma16816(float c[4], const unsigned a[4],
                                         const unsigned b0, const unsigned b1) {
    asm volatile(
        "mma.sync.aligned.m16n8k16.row.col.f32.bf16.bf16.f32 "
        "{%0,%1,%2,%3}, {%4,%5,%6,%7}, {%8,%9}, {%0,%1,%2,%3};\n"
        : "+f"(c[0]), "+f"(c[1]), "+f"(c[2]), "+f"(c[3])
        : "r"(a[0]), "r"(a[1]), "r"(a[2]), "r"(a[3]), "r"(b0), "r"(b1));
}

__device__ __forceinline__ void ldmatrix_x4(unsigned r[4], uint32_t addr) {
    asm volatile(
        "ldmatrix.sync.aligned.m8n8.x4.shared.b16 {%0,%1,%2,%3}, [%4];\n"
        : "=r"(r[0]), "=r"(r[1]), "=r"(r[2]), "=r"(r[3])
        : "r"(addr));
}

__device__ __forceinline__ float gelu_erf(float v) {
    return 0.5f * v * (1.0f + erff(v * 0.70710678118654752f));
}

// ---------------------------------------------------------------------------
// One GEMM layer: out = gelu(in[64,K] @ W[K,N] + bias).
// Warp grid 2(m) x 4(n); per pass warp owns CW=CHUNK/4 cols (NF=CW/8 frags).
// B loaded as uint4 (two kt per load), prefetched 2 pairs (4 kt) ahead.
// ---------------------------------------------------------------------------
template <int K, int N, int CHUNK>
__device__ __forceinline__ void gemm_layer(const __nv_bfloat16* inBuf,
                                           __nv_bfloat16* outBuf,
                                           const __nv_bfloat16* __restrict__ Wp,
                                           const float* __restrict__ s_bias) {
    constexpr int NPASS = N / CHUNK;
    constexpr int CW  = CHUNK / 4;
    constexpr int NF  = CW / 8;
    constexpr int KT  = K / 16;
    constexpr int KTP = KT / 2;

    const int tid  = threadIdx.x;
    const int lane = tid & 31;
    const int wid  = tid >> 5;
    const int wm   = wid & 1;
    const int wn   = wid >> 1;

    uint32_t sA = (uint32_t)__cvta_generic_to_shared(inBuf);
    const int arow     = wm * 32 + (lane & 15);
    const int acol_off = (lane >> 4) * 8;
    const uint32_t aBase = sA + (uint32_t)((arow * LD + acol_off) * 2);

    const uint4* bb = (const uint4*)Wp;   // one uint4 per (nt,ktp,lane)

#pragma unroll
    for (int p = 0; p < NPASS; ++p) {
        float acc[2][NF][4];
#pragma unroll
        for (int mi = 0; mi < 2; ++mi)
#pragma unroll
            for (int nf = 0; nf < NF; ++nf)
#pragma unroll
                for (int q = 0; q < 4; ++q) acc[mi][nf][q] = 0.f;

        const int colbase = p * CHUNK + wn * CW;
        const int ntbase  = colbase >> 3;
        // lane-resolved base index into uint4 array
        const uint4* bwarp = bb + (size_t)ntbase * KTP * 32 + lane;

        uint4 b0[NF], b1[NF];
#pragma unroll
        for (int nf = 0; nf < NF; ++nf)
            b0[nf] = __ldg(bwarp + (size_t)nf * KTP * 32);
        if (KTP > 1) {
#pragma unroll
            for (int nf = 0; nf < NF; ++nf)
                b1[nf] = __ldg(bwarp + (size_t)nf * KTP * 32 + 32);
        }

#pragma unroll
        for (int ktp = 0; ktp < KTP; ++ktp) {
            // prefetch pair ktp+2
            uint4 bn[NF];
            if (ktp + 2 < KTP) {
#pragma unroll
                for (int nf = 0; nf < NF; ++nf)
                    bn[nf] = __ldg(bwarp + (size_t)nf * KTP * 32 + (ktp + 2) * 32);
            }

            // kt even
            {
                unsigned a[2][4];
                uint32_t addr0 = aBase + (uint32_t)((2 * ktp) * 32);
                ldmatrix_x4(a[0], addr0);
                ldmatrix_x4(a[1], addr0 + 16 * LD * 2);
#pragma unroll
                for (int nf = 0; nf < NF; ++nf) {
                    mma16816(acc[0][nf], a[0], b0[nf].x, b0[nf].y);
                    mma16816(acc[1][nf], a[1], b0[nf].x, b0[nf].y);
                }
            }
            // kt odd
            {
                unsigned a[2][4];
                uint32_t addr0 = aBase + (uint32_t)((2 * ktp + 1) * 32);
                ldmatrix_x4(a[0], addr0);
                ldmatrix_x4(a[1], addr0 + 16 * LD * 2);
#pragma unroll
                for (int nf = 0; nf < NF; ++nf) {
                    mma16816(acc[0][nf], a[0], b0[nf].z, b0[nf].w);
                    mma16816(acc[1][nf], a[1], b0[nf].z, b0[nf].w);
                }
            }

#pragma unroll
            for (int nf = 0; nf < NF; ++nf) b0[nf] = b1[nf];
            if (ktp + 2 < KTP) {
#pragma unroll
                for (int nf = 0; nf < NF; ++nf) b1[nf] = bn[nf];
            }
        }

        // epilogue: bias + gelu + bf16 store
        const int r0 = wm * 32 + (lane >> 2);
        const int cb = colbase + (lane & 3) * 2;
#pragma unroll
        for (int nf = 0; nf < NF; ++nf) {
            const int c = cb + nf * 8;
            const float bi0 = s_bias[c];
            const float bi1 = s_bias[c + 1];
#pragma unroll
            for (int mi = 0; mi < 2; ++mi) {
                const int row = r0 + mi * 16;
                float v0 = gelu_erf(acc[mi][nf][0] + bi0);
                float v1 = gelu_erf(acc[mi][nf][1] + bi1);
                float v2 = gelu_erf(acc[mi][nf][2] + bi0);
                float v3 = gelu_erf(acc[mi][nf][3] + bi1);
                *(__nv_bfloat162*)(outBuf + row * LD + c) =
                    __floats2bfloat162_rn(v0, v1);
                *(__nv_bfloat162*)(outBuf + (row + 8) * LD + c) =
                    __floats2bfloat162_rn(v2, v3);
            }
        }
    }
}

// ---------------------------------------------------------------------------
// Fused kernel
// ---------------------------------------------------------------------------
__global__ void __launch_bounds__(NTHREADS, 2)
fused_mlp_kernel(const float* __restrict__ x,
                 const float* __restrict__ ln_g,
                 const float* __restrict__ ln_b,
                 const float* __restrict__ b1,
                 const float* __restrict__ b2,
                 const float* __restrict__ b3,
                 const float* __restrict__ W4,
                 const float* __restrict__ b4,
                 float* __restrict__ out) {
    extern __shared__ __align__(16) char smem_raw[];
    __nv_bfloat16* bufA = (__nv_bfloat16*)smem_raw;                 // [64][392]
    __nv_bfloat16* bufB = bufA + ROWS_TILE * LD;                    // [64][392]
    float* s_bias = (float*)(bufB + ROWS_TILE * LD);                // [384]

    const int tid  = threadIdx.x;
    const int lane = tid & 31;
    const int wid  = tid >> 5;
    const long row0 = (long)blockIdx.x * ROWS_TILE;
    const int m = (int)(row0 / ROWS_PER_M);

    // ------------------- Stage 0: LayerNorm -> bufA (bf16) -----------------
    {
        float4 g4[3], bb4[3];
#pragma unroll
        for (int j = 0; j < 3; ++j) {
            g4[j]  = ((const float4*)(ln_g + m * 384))[j * 32 + lane];
            bb4[j] = ((const float4*)(ln_b + m * 384))[j * 32 + lane];
        }
#pragma unroll
        for (int r = wid; r < ROWS_TILE; r += 8) {
            const float4* xr = (const float4*)(x + (row0 + r) * 384);
            float4 v[3];
            float s = 0.f, q = 0.f;
#pragma unroll
            for (int j = 0; j < 3; ++j) {
                v[j] = xr[j * 32 + lane];
                s += v[j].x + v[j].y + v[j].z + v[j].w;
                q += v[j].x * v[j].x + v[j].y * v[j].y +
                     v[j].z * v[j].z + v[j].w * v[j].w;
            }
#pragma unroll
            for (int off = 16; off; off >>= 1) {
                s += __shfl_xor_sync(0xffffffffu, s, off);
                q += __shfl_xor_sync(0xffffffffu, q, off);
            }
            const float mu   = s * (1.0f / 384.0f);
            const float var  = q * (1.0f / 384.0f) - mu * mu;
            const float rinv = rsqrtf(var + 1e-5f);
#pragma unroll
            for (int j = 0; j < 3; ++j) {
                const int c = (j * 32 + lane) * 4;
                float y0 = (v[j].x - mu) * rinv * g4[j].x + bb4[j].x;
                float y1 = (v[j].y - mu) * rinv * g4[j].y + bb4[j].y;
                float y2 = (v[j].z - mu) * rinv * g4[j].z + bb4[j].z;
                float y3 = (v[j].w - mu) * rinv * g4[j].w + bb4[j].w;
                *(__nv_bfloat162*)(bufA + r * LD + c)     = __floats2bfloat162_rn(y0, y1);
                *(__nv_bfloat162*)(bufA + r * LD + c + 2) = __floats2bfloat162_rn(y2, y3);
            }
        }
    }

    const __nv_bfloat16* WpBase = g_packedW + (size_t)m * MOD_STRIDE;

    // ------------------- Layer 1: 384 -> 384 (3 passes of 128) -------------
    __syncthreads();
    for (int i = tid; i < 384; i += NTHREADS) s_bias[i] = b1[m * 384 + i];
    __syncthreads();
    gemm_layer<384, 384, 128>(bufA, bufB, WpBase, s_bias);

    // ------------------- Layer 2: 384 -> 192 (2 passes of 96) --------------
    __syncthreads();
    if (tid < 192) s_bias[tid] = b2[m * 192 + tid];
    __syncthreads();
    gemm_layer<384, 192, 96>(bufB, bufA, WpBase + OFF_L2, s_bias);

    // ------------------- Layer 3: 192 -> 96 (1 pass of 96) -----------------
    __syncthreads();
    if (tid < 96) s_bias[tid] = b3[m * 96 + tid];
    __syncthreads();
    gemm_layer<192, 96, 96>(bufA, bufB, WpBase + OFF_L3, s_bias);

    // ------------------- Layer 4: 96 -> 2 + log_softmax --------------------
    __syncthreads();
    {
        const int r    = tid >> 2;
        const int part = tid & 3;
        const float* w4 = W4 + m * 96 * 2;
        const __nv_bfloat16* hrow = bufB + r * LD;
        float z0 = 0.f, z1 = 0.f;
#pragma unroll
        for (int kk = 0; kk < 24; ++kk) {
            const int k = part * 24 + kk;
            float a = __bfloat162float(hrow[k]);
            z0 += a * w4[k * 2 + 0];
            z1 += a * w4[k * 2 + 1];
        }
        z0 += __shfl_xor_sync(0xffffffffu, z0, 1);
        z0 += __shfl_xor_sync(0xffffffffu, z0, 2);
        z1 += __shfl_xor_sync(0xffffffffu, z1, 1);
        z1 += __shfl_xor_sync(0xffffffffu, z1, 2);
        if (part == 0) {
            z0 += b4[m * 2 + 0];
            z1 += b4[m * 2 + 1];
            const float mx  = fmaxf(z0, z1);
            const float lse = mx + logf(expf(z0 - mx) + expf(z1 - mx));
            float* o = out + (row0 + r) * 2;
            o[0] = z0 - lse;
            o[1] = z1 - lse;
        }
    }
}

// ---------------------------------------------------------------------------
// Launch
// ---------------------------------------------------------------------------
extern "C" void kernel_launch(void* const* d_in, const int* in_sizes, int n_in,
                              void* d_out, int out_size) {
    const float* x    = (const float*)d_in[0];
    const float* ln_g = (const float*)d_in[1];
    const float* ln_b = (const float*)d_in[2];
    const float* W1   = (const float*)d_in[3];
    const float* b1   = (const float*)d_in[4];
    const float* W2   = (const float*)d_in[5];
    const float* b2   = (const float*)d_in[6];
    const float* W3   = (const float*)d_in[7];
    const float* b3   = (const float*)d_in[8];
    const float* W4   = (const float*)d_in[9];
    const float* b4   = (const float*)d_in[10];
    float* out        = (float*)d_out;

    const int packTotal = 2 * MOD_STRIDE;
    pack_weights_kernel<<<(packTotal + 255) / 256, 256>>>(W1, W2, W3);

    const int smem_bytes = 2 * ROWS_TILE * LD * (int)sizeof(__nv_bfloat16)
                         + 384 * (int)sizeof(float);
    cudaFuncSetAttribute(fused_mlp_kernel,
                         cudaFuncAttributeMaxDynamicSharedMemorySize, smem_bytes);
    fused_mlp_kernel<<<RTOT / ROWS_TILE, NTHREADS, smem_bytes>>>(
        x, ln_g, ln_b, b1, b2, b3, W4, b4, out);
}

// round 6
// speedup vs baseline: 2.1232x; 1.2006x over previous
#include <cuda_runtime.h>
#include <cuda_bf16.h>
#include <math.h>
#include <stdint.h>

// ---------------------------------------------------------------------------
// PredictorLG fused MLP:  LN -> (GEMM+GELU)x3 -> GEMM(->2) -> log_softmax
// R6: issue-slot diet. HW tanh.approx GELU (6 ops vs ~20 for erff),
// copy-free circular B prefetch. 64 rows/CTA, 2 CTAs/SM, warp grid 2x4.
// ---------------------------------------------------------------------------

#define ROWS_TILE   64
#define NTHREADS    256
#define LD          392           // padded activation row stride (halfs)
#define RTOT        262144
#define ROWS_PER_M  131072

#define S1 (384*384)
#define S2 (384*192)
#define S3 (192*96)
#define MOD_STRIDE (S1+S2+S3)
#define OFF_L2 (S1)
#define OFF_L3 (S1+S2)

__device__ __align__(16) __nv_bfloat16 g_packedW[2 * MOD_STRIDE];

// ---------------------------------------------------------------------------
// Weight repack: W[k][n] fp32 -> pair-kt B-fragment layout (16B/lane covers
// two consecutive kt):
//   dst = base + ((nt*KTP + ktp)*32 + lane)*8 + (kt&1)*4 + reg*2 + i
//   lane = (n%8)*4 + ((k%8)>>1);  reg = (k>>3)&1;  i = k&1
// ---------------------------------------------------------------------------
__global__ void pack_weights_kernel(const float* __restrict__ W1,
                                    const float* __restrict__ W2,
                                    const float* __restrict__ W3) {
    int idx = blockIdx.x * blockDim.x + threadIdx.x;
    const float* src;
    int K, N, r, m, layerOff;
    if (idx < 2 * S1) {
        m = idx / S1; r = idx % S1; K = 384; N = 384;
        src = W1 + m * S1; layerOff = 0;
    } else if (idx < 2 * (S1 + S2)) {
        int e = idx - 2 * S1;
        m = e / S2; r = e % S2; K = 384; N = 192;
        src = W2 + m * S2; layerOff = OFF_L2;
    } else if (idx < 2 * (S1 + S2 + S3)) {
        int e = idx - 2 * (S1 + S2);
        m = e / S3; r = e % S3; K = 192; N = 96;
        src = W3 + m * S3; layerOff = OFF_L3;
    } else {
        return;
    }
    int k = r / N, n = r % N;
    int kt  = k >> 4;
    int ktp = kt >> 1;
    int KTP = K >> 5;
    int nt  = n >> 3;
    int lane = (n & 7) * 4 + ((k & 7) >> 1);
    int reg  = (k >> 3) & 1;
    int i    = k & 1;
    int dst  = m * MOD_STRIDE + layerOff +
               ((nt * KTP + ktp) * 32 + lane) * 8 + (kt & 1) * 4 + reg * 2 + i;
    g_packedW[dst] = __float2bfloat16(src[k * N + n]);
}

// ---------------------------------------------------------------------------
// mma / ldmatrix / gelu helpers
// ---------------------------------------------------------------------------
__device__ __forceinline__ void mma16816(float c[4], const unsigned a[4],
                                         const unsigned b0, const unsigned b1) {
    asm volatile(
        "mma.sync.aligned.m16n8k16.row.col.f32.bf16.bf16.f32 "
        "{%0,%1,%2,%3}, {%4,%5,%6,%7}, {%8,%9}, {%0,%1,%2,%3};\n"
        : "+f"(c[0]), "+f"(c[1]), "+f"(c[2]), "+f"(c[3])
        : "r"(a[0]), "r"(a[1]), "r"(a[2]), "r"(a[3]), "r"(b0), "r"(b1));
}

__device__ __forceinline__ void ldmatrix_x4(unsigned r[4], uint32_t addr) {
    asm volatile(
        "ldmatrix.sync.aligned.m8n8.x4.shared.b16 {%0,%1,%2,%3}, [%4];\n"
        : "=r"(r[0]), "=r"(r[1]), "=r"(r[2]), "=r"(r[3])
        : "r"(addr));
}

// fast GELU: tanh approximation with HW MUFU.TANH (max err ~1e-3 abs,
// far below bf16 storage quantization already present)
__device__ __forceinline__ float gelu_fast(float v) {
    float u = v * (0.7978845608028654f + 0.0447149985f * v * v);
    float t;
    asm("tanh.approx.f32 %0, %1;" : "=f"(t) : "f"(u));
    float h = 0.5f * v;
    return h + h * t;
}

// ---------------------------------------------------------------------------
// One GEMM layer: out = gelu(in[64,K] @ W[K,N] + bias).
// Warp grid 2(m) x 4(n); B as uint4 (two kt per load), 3-slot circular
// prefetch (2 pairs = 4 kt ahead), static indices under full unroll.
// ---------------------------------------------------------------------------
template <int K, int N, int CHUNK>
__device__ __forceinline__ void gemm_layer(const __nv_bfloat16* inBuf,
                                           __nv_bfloat16* outBuf,
                                           const __nv_bfloat16* __restrict__ Wp,
                                           const float* __restrict__ s_bias) {
    constexpr int NPASS = N / CHUNK;
    constexpr int CW  = CHUNK / 4;
    constexpr int NF  = CW / 8;
    constexpr int KT  = K / 16;
    constexpr int KTP = KT / 2;

    const int tid  = threadIdx.x;
    const int lane = tid & 31;
    const int wid  = tid >> 5;
    const int wm   = wid & 1;
    const int wn   = wid >> 1;

    uint32_t sA = (uint32_t)__cvta_generic_to_shared(inBuf);
    const int arow     = wm * 32 + (lane & 15);
    const int acol_off = (lane >> 4) * 8;
    const uint32_t aBase = sA + (uint32_t)((arow * LD + acol_off) * 2);

    const uint4* bb = (const uint4*)Wp;

#pragma unroll
    for (int p = 0; p < NPASS; ++p) {
        float acc[2][NF][4];
#pragma unroll
        for (int mi = 0; mi < 2; ++mi)
#pragma unroll
            for (int nf = 0; nf < NF; ++nf)
#pragma unroll
                for (int q = 0; q < 4; ++q) acc[mi][nf][q] = 0.f;

        const int colbase = p * CHUNK + wn * CW;
        const int ntbase  = colbase >> 3;
        const uint4* bwarp = bb + (size_t)ntbase * KTP * 32 + lane;

        // 3-slot circular prefetch buffer, static indices (full unroll)
        uint4 bf[3][NF];
#pragma unroll
        for (int nf = 0; nf < NF; ++nf)
            bf[0][nf] = __ldg(bwarp + (size_t)nf * KTP * 32);
        if (KTP > 1) {
#pragma unroll
            for (int nf = 0; nf < NF; ++nf)
                bf[1][nf] = __ldg(bwarp + (size_t)nf * KTP * 32 + 32);
        }

#pragma unroll
        for (int ktp = 0; ktp < KTP; ++ktp) {
            const int cur = ktp % 3;
            const int nxt = (ktp + 2) % 3;
            if (ktp + 2 < KTP) {
#pragma unroll
                for (int nf = 0; nf < NF; ++nf)
                    bf[nxt][nf] = __ldg(bwarp + (size_t)nf * KTP * 32 + (ktp + 2) * 32);
            }
            // kt even
            {
                unsigned a[2][4];
                uint32_t addr0 = aBase + (uint32_t)((2 * ktp) * 32);
                ldmatrix_x4(a[0], addr0);
                ldmatrix_x4(a[1], addr0 + 16 * LD * 2);
#pragma unroll
                for (int nf = 0; nf < NF; ++nf) {
                    mma16816(acc[0][nf], a[0], bf[cur][nf].x, bf[cur][nf].y);
                    mma16816(acc[1][nf], a[1], bf[cur][nf].x, bf[cur][nf].y);
                }
            }
            // kt odd
            {
                unsigned a[2][4];
                uint32_t addr0 = aBase + (uint32_t)((2 * ktp + 1) * 32);
                ldmatrix_x4(a[0], addr0);
                ldmatrix_x4(a[1], addr0 + 16 * LD * 2);
#pragma unroll
                for (int nf = 0; nf < NF; ++nf) {
                    mma16816(acc[0][nf], a[0], bf[cur][nf].z, bf[cur][nf].w);
                    mma16816(acc[1][nf], a[1], bf[cur][nf].z, bf[cur][nf].w);
                }
            }
        }

        // epilogue: bias + fast gelu + bf16 store
        const int r0 = wm * 32 + (lane >> 2);
        const int cb = colbase + (lane & 3) * 2;
#pragma unroll
        for (int nf = 0; nf < NF; ++nf) {
            const int c = cb + nf * 8;
            const float bi0 = s_bias[c];
            const float bi1 = s_bias[c + 1];
#pragma unroll
            for (int mi = 0; mi < 2; ++mi) {
                const int row = r0 + mi * 16;
                float v0 = gelu_fast(acc[mi][nf][0] + bi0);
                float v1 = gelu_fast(acc[mi][nf][1] + bi1);
                float v2 = gelu_fast(acc[mi][nf][2] + bi0);
                float v3 = gelu_fast(acc[mi][nf][3] + bi1);
                *(__nv_bfloat162*)(outBuf + row * LD + c) =
                    __floats2bfloat162_rn(v0, v1);
                *(__nv_bfloat162*)(outBuf + (row + 8) * LD + c) =
                    __floats2bfloat162_rn(v2, v3);
            }
        }
    }
}

// ---------------------------------------------------------------------------
// Fused kernel
// ---------------------------------------------------------------------------
__global__ void __launch_bounds__(NTHREADS, 2)
fused_mlp_kernel(const float* __restrict__ x,
                 const float* __restrict__ ln_g,
                 const float* __restrict__ ln_b,
                 const float* __restrict__ b1,
                 const float* __restrict__ b2,
                 const float* __restrict__ b3,
                 const float* __restrict__ W4,
                 const float* __restrict__ b4,
                 float* __restrict__ out) {
    extern __shared__ __align__(16) char smem_raw[];
    __nv_bfloat16* bufA = (__nv_bfloat16*)smem_raw;                 // [64][392]
    __nv_bfloat16* bufB = bufA + ROWS_TILE * LD;                    // [64][392]
    float* s_bias = (float*)(bufB + ROWS_TILE * LD);                // [384]

    const int tid  = threadIdx.x;
    const int lane = tid & 31;
    const int wid  = tid >> 5;
    const long row0 = (long)blockIdx.x * ROWS_TILE;
    const int m = (int)(row0 / ROWS_PER_M);

    // ------------------- Stage 0: LayerNorm -> bufA (bf16) -----------------
    {
        float4 g4[3], bb4[3];
#pragma unroll
        for (int j = 0; j < 3; ++j) {
            g4[j]  = ((const float4*)(ln_g + m * 384))[j * 32 + lane];
            bb4[j] = ((const float4*)(ln_b + m * 384))[j * 32 + lane];
        }
#pragma unroll
        for (int r = wid; r < ROWS_TILE; r += 8) {
            const float4* xr = (const float4*)(x + (row0 + r) * 384);
            float4 v[3];
            float s = 0.f, q = 0.f;
#pragma unroll
            for (int j = 0; j < 3; ++j) {
                v[j] = xr[j * 32 + lane];
                s += v[j].x + v[j].y + v[j].z + v[j].w;
                q += v[j].x * v[j].x + v[j].y * v[j].y +
                     v[j].z * v[j].z + v[j].w * v[j].w;
            }
#pragma unroll
            for (int off = 16; off; off >>= 1) {
                s += __shfl_xor_sync(0xffffffffu, s, off);
                q += __shfl_xor_sync(0xffffffffu, q, off);
            }
            const float mu   = s * (1.0f / 384.0f);
            const float var  = q * (1.0f / 384.0f) - mu * mu;
            const float rinv = rsqrtf(var + 1e-5f);
#pragma unroll
            for (int j = 0; j < 3; ++j) {
                const int c = (j * 32 + lane) * 4;
                float y0 = (v[j].x - mu) * rinv * g4[j].x + bb4[j].x;
                float y1 = (v[j].y - mu) * rinv * g4[j].y + bb4[j].y;
                float y2 = (v[j].z - mu) * rinv * g4[j].z + bb4[j].z;
                float y3 = (v[j].w - mu) * rinv * g4[j].w + bb4[j].w;
                *(__nv_bfloat162*)(bufA + r * LD + c)     = __floats2bfloat162_rn(y0, y1);
                *(__nv_bfloat162*)(bufA + r * LD + c + 2) = __floats2bfloat162_rn(y2, y3);
            }
        }
    }

    const __nv_bfloat16* WpBase = g_packedW + (size_t)m * MOD_STRIDE;

    // ------------------- Layer 1: 384 -> 384 (3 passes of 128) -------------
    __syncthreads();
    for (int i = tid; i < 384; i += NTHREADS) s_bias[i] = b1[m * 384 + i];
    __syncthreads();
    gemm_layer<384, 384, 128>(bufA, bufB, WpBase, s_bias);

    // ------------------- Layer 2: 384 -> 192 (2 passes of 96) --------------
    __syncthreads();
    if (tid < 192) s_bias[tid] = b2[m * 192 + tid];
    __syncthreads();
    gemm_layer<384, 192, 96>(bufB, bufA, WpBase + OFF_L2, s_bias);

    // ------------------- Layer 3: 192 -> 96 (1 pass of 96) -----------------
    __syncthreads();
    if (tid < 96) s_bias[tid] = b3[m * 96 + tid];
    __syncthreads();
    gemm_layer<192, 96, 96>(bufA, bufB, WpBase + OFF_L3, s_bias);

    // ------------------- Layer 4: 96 -> 2 + log_softmax --------------------
    __syncthreads();
    {
        const int r    = tid >> 2;
        const int part = tid & 3;
        const float* w4 = W4 + m * 96 * 2;
        const __nv_bfloat16* hrow = bufB + r * LD;
        float z0 = 0.f, z1 = 0.f;
#pragma unroll
        for (int kk = 0; kk < 24; ++kk) {
            const int k = part * 24 + kk;
            float a = __bfloat162float(hrow[k]);
            z0 += a * w4[k * 2 + 0];
            z1 += a * w4[k * 2 + 1];
        }
        z0 += __shfl_xor_sync(0xffffffffu, z0, 1);
        z0 += __shfl_xor_sync(0xffffffffu, z0, 2);
        z1 += __shfl_xor_sync(0xffffffffu, z1, 1);
        z1 += __shfl_xor_sync(0xffffffffu, z1, 2);
        if (part == 0) {
            z0 += b4[m * 2 + 0];
            z1 += b4[m * 2 + 1];
            const float mx  = fmaxf(z0, z1);
            const float lse = mx + logf(expf(z0 - mx) + expf(z1 - mx));
            float* o = out + (row0 + r) * 2;
            o[0] = z0 - lse;
            o[1] = z1 - lse;
        }
    }
}

// ---------------------------------------------------------------------------
// Launch
// ---------------------------------------------------------------------------
extern "C" void kernel_launch(void* const* d_in, const int* in_sizes, int n_in,
                              void* d_out, int out_size) {
    const float* x    = (const float*)d_in[0];
    const float* ln_g = (const float*)d_in[1];
    const float* ln_b = (const float*)d_in[2];
    const float* W1   = (const float*)d_in[3];
    const float* b1   = (const float*)d_in[4];
    const float* W2   = (const float*)d_in[5];
    const float* b2   = (const float*)d_in[6];
    const float* W3   = (const float*)d_in[7];
    const float* b3   = (const float*)d_in[8];
    const float* W4   = (const float*)d_in[9];
    const float* b4   = (const float*)d_in[10];
    float* out        = (float*)d_out;

    const int packTotal = 2 * MOD_STRIDE;
    pack_weights_kernel<<<(packTotal + 255) / 256, 256>>>(W1, W2, W3);

    const int smem_bytes = 2 * ROWS_TILE * LD * (int)sizeof(__nv_bfloat16)
                         + 384 * (int)sizeof(float);
    cudaFuncSetAttribute(fused_mlp_kernel,
                         cudaFuncAttributeMaxDynamicSharedMemorySize, smem_bytes);
    fused_mlp_kernel<<<RTOT / ROWS_TILE, NTHREADS, smem_bytes>>>(
        x, ln_g, ln_b, b1, b2, b3, W4, b4, out);
}